// round 15
// baseline (speedup 1.0000x reference)
#include <cuda_runtime.h>
#include <cuda_fp16.h>
#include <cstdint>

#define B_ 32
#define L_ 2048
#define D_ 768
#define H_ 512
#define M_ (B_*L_)   // 65536 tokens

// ---- scratch (__device__ globals per allocation rules) ----
__device__ __half g_h[(size_t)M_ * H_];         // 64 MB intermediate h (fp16)
__device__ __half g_a16[(size_t)M_ * D_];       // hidden pre-converted fp16 (96 MB)
__device__ __half g_w1t[H_ * D_];               // W1 transposed, fp16
__device__ float g_sum[H_];
__device__ float g_sumsq[H_];
__device__ float g_scale[H_];
__device__ float g_shift[H_];
__device__ float g_counts[B_];
__device__ float g_pooled[B_ * H_];

// =====================================================================
// helpers
// =====================================================================
__device__ __forceinline__ void mma16816(float* c, const uint32_t* a,
                                         const uint32_t* b) {
    asm volatile(
        "mma.sync.aligned.m16n8k16.row.col.f32.f16.f16.f32 "
        "{%0,%1,%2,%3}, {%4,%5,%6,%7}, {%8,%9}, {%0,%1,%2,%3};"
        : "+f"(c[0]), "+f"(c[1]), "+f"(c[2]), "+f"(c[3])
        : "r"(a[0]), "r"(a[1]), "r"(a[2]), "r"(a[3]), "r"(b[0]), "r"(b[1]));
}

__device__ __forceinline__ void ldsm4(uint32_t* r, uint32_t addr) {
    asm volatile("ldmatrix.sync.aligned.m8n8.x4.shared.b16 {%0,%1,%2,%3}, [%4];"
        : "=r"(r[0]), "=r"(r[1]), "=r"(r[2]), "=r"(r[3]) : "r"(addr));
}

#define CP_ASYNC16(dst, src) \
    asm volatile("cp.async.cg.shared.global [%0], [%1], 16;" \
                 :: "r"(dst), "l"(src) : "memory")
#define CP_COMMIT()  asm volatile("cp.async.commit_group;" ::: "memory")
#define CP_WAIT0()   asm volatile("cp.async.wait_group 0;" ::: "memory")

__device__ __forceinline__ uint32_t smem_u32(const void* p) {
    uint32_t a;
    asm("{ .reg .u64 t; cvta.to.shared.u64 t, %1; cvt.u32.u64 %0, t; }"
        : "=r"(a) : "l"(p));
    return a;
}

__device__ __forceinline__ uint32_t f22u(float x, float y) {
    __half2 h = __floats2half2_rn(x, y);
    return *(uint32_t*)&h;
}

// =====================================================================
// 0) zero accumulators
// =====================================================================
__global__ void k_zero() {
    int i = blockIdx.x * blockDim.x + threadIdx.x;
    if (i < H_) { g_sum[i] = 0.f; g_sumsq[i] = 0.f; }
    if (i < B_ * H_) g_pooled[i] = 0.f;
}

// =====================================================================
// 1) per-batch valid-token counts
// =====================================================================
__global__ void k_counts(const int* __restrict__ mask) {
    __shared__ float red[256];
    int b = blockIdx.x;
    float s = 0.f;
    for (int l = threadIdx.x; l < L_; l += 256)
        s += (float)mask[b * L_ + l];
    red[threadIdx.x] = s;
    __syncthreads();
    for (int o = 128; o > 0; o >>= 1) {
        if (threadIdx.x < o) red[threadIdx.x] += red[threadIdx.x + o];
        __syncthreads();
    }
    if (threadIdx.x == 0) g_counts[b] = red[0];
}

// =====================================================================
// 1b) prep: W1 (D,H) -> transposed fp16 (H,D)
// =====================================================================
__global__ void k_prepW1(const float* __restrict__ W1) {
    int idx = blockIdx.x * 256 + threadIdx.x;   // (n, k2) pairs
    if (idx >= H_ * (D_ / 2)) return;
    int n  = idx / (D_ / 2);
    int k2 = idx % (D_ / 2);
    float f0 = W1[(size_t)(2 * k2)     * H_ + n];
    float f1 = W1[(size_t)(2 * k2 + 1) * H_ + n];
    ((uint32_t*)g_w1t)[idx] = f22u(f0, f1);
}

// =====================================================================
// 1c) prep: hidden fp32 -> fp16 (row-major [M][D])
// =====================================================================
__global__ __launch_bounds__(256) void k_prepA(const float4* __restrict__ A4) {
    int idx = blockIdx.x * 256 + threadIdx.x;
    if (idx >= M_ * D_ / 4) return;
    float4 v = A4[idx];
    ((uint2*)g_a16)[idx] = make_uint2(f22u(v.x, v.y), f22u(v.z, v.w));
}

// =====================================================================
// 2) GEMM1: h = hidden @ W1 + b1 via fp16 mma.sync + ldmatrix
//    CTA tile 128x128x32, 128 threads, 4 warps of 64x64, dbl-buffered,
//    2 CTAs/SM, pure cp.async mainloop.
//    Fused epilogue: +b1, store h (fp16), masked BN stats.
// =====================================================================
#define BKC 32
#define NCHUNK (D_ / BKC)       // 24
// SMEM per buffer: rows padded to 80 B (64 B data + 16 pad)
// A 128*80=10240 B, B 128*80=10240 B -> 20480 B per buffer
#define BUFB   20480
#define BOFF   10240
#define SMEM_GEMM (2 * BUFB)    // 40960 bytes

__global__ __launch_bounds__(128, 2) void k_gemm_mma(
    const float* __restrict__ bias1,
    const int* __restrict__ mask)
{
    extern __shared__ uint32_t S[];
    const uint32_t sbase = smem_u32(S);
    const int tid  = threadIdx.x;
    const int lane = tid & 31;
    const int wid  = tid >> 5;        // 0..3
    const int warp_m = wid & 1;       // 2 m-groups of 64 rows
    const int warp_n = wid >> 1;      // 2 n-groups of 64 cols
    const int m0 = blockIdx.y * 128;
    const int n0 = blockIdx.x * 128;

    // loader mapping: 1 thread per row (128 rows), 64 B per chunk
    const char* ag = (const char*)(g_a16 + (size_t)(m0 + tid) * D_);
    const char* bg = (const char*)(g_w1t + (size_t)(n0 + tid) * D_);
    const uint32_t stoff = (uint32_t)tid * 80;

    // fragment ldmatrix base offsets (bytes)
    const uint32_t aoff = (uint32_t)(warp_m * 64 + (lane & 15)) * 80 + ((lane >> 4) << 4);
    const uint32_t boff = BOFF + (uint32_t)(warp_n * 64 + lane) * 80;

    float c[4][8][4];
    #pragma unroll
    for (int i = 0; i < 4; i++)
        #pragma unroll
        for (int j = 0; j < 8; j++)
            #pragma unroll
            for (int q = 0; q < 4; q++) c[i][j][q] = 0.f;

    // ---- prologue: load chunk 0 into buffer 0 ----
    #pragma unroll
    for (int j = 0; j < 4; j++) {
        CP_ASYNC16(sbase + stoff + j * 16,        ag + j * 16);
        CP_ASYNC16(sbase + BOFF + stoff + j * 16, bg + j * 16);
    }
    CP_COMMIT();
    CP_WAIT0();
    __syncthreads();

    for (int cidx = 0; cidx < NCHUNK; ++cidx) {
        const int cur = cidx & 1;
        const int nxt = cur ^ 1;
        if (cidx + 1 < NCHUNK) {
            const int off = (cidx + 1) * 64;      // 32 halfs = 64 B per chunk
            const uint32_t nb = sbase + nxt * BUFB;
            #pragma unroll
            for (int j = 0; j < 4; j++) {
                CP_ASYNC16(nb + stoff + j * 16,        ag + off + j * 16);
                CP_ASYNC16(nb + BOFF + stoff + j * 16, bg + off + j * 16);
            }
            CP_COMMIT();
        }

        // ---- compute on cur buffer ----
        {
            const uint32_t st = sbase + cur * BUFB;
            #pragma unroll
            for (int ks = 0; ks < 2; ++ks) {            // two k16 groups
                const uint32_t kb = ks * 32;
                uint32_t ah[4][4];
                uint32_t bq0[4], bq1[4], bq2[4], bq3[4];
                #pragma unroll
                for (int mi = 0; mi < 4; mi++)
                    ldsm4(ah[mi], st + aoff + mi * 16 * 80 + kb);
                ldsm4(bq0, st + boff + kb);
                ldsm4(bq1, st + boff + kb + 16);
                ldsm4(bq2, st + boff + 32 * 80 + kb);
                ldsm4(bq3, st + boff + 32 * 80 + kb + 16);
                #pragma unroll
                for (int mi = 0; mi < 4; mi++) {
                    #pragma unroll
                    for (int ni = 0; ni < 4; ni++) {
                        uint32_t bf[2] = { bq0[ni], bq1[ni] };
                        mma16816(c[mi][ni], ah[mi], bf);
                    }
                    #pragma unroll
                    for (int ni = 0; ni < 4; ni++) {
                        uint32_t bf[2] = { bq2[ni], bq3[ni] };
                        mma16816(c[mi][ni + 4], ah[mi], bf);
                    }
                }
            }
        }

        if (cidx + 1 < NCHUNK) CP_WAIT0();
        __syncthreads();
    }

    // ---- epilogue: + b1, store h (fp16), fused masked stats ----
    const int rbase = m0 + warp_m * 64 + (lane >> 2);
    const int cb    = warp_n * 64 + (lane & 3) * 2;
    float mk[8];
    #pragma unroll
    for (int mi = 0; mi < 4; mi++) {
        mk[2*mi]   = (float)mask[rbase + mi * 16];
        mk[2*mi+1] = (float)mask[rbase + mi * 16 + 8];
    }

    #pragma unroll
    for (int ni = 0; ni < 8; ni++) {
        int col = n0 + cb + ni * 8;
        float2 bb = *(const float2*)&bias1[col];
        float sx = 0.f, sy = 0.f, qx = 0.f, qy = 0.f;
        #pragma unroll
        for (int mi = 0; mi < 4; mi++) {
            int r0 = rbase + mi * 16;
            float h0 = c[mi][ni][0] + bb.x, h1 = c[mi][ni][1] + bb.y;
            float h2 = c[mi][ni][2] + bb.x, h3 = c[mi][ni][3] + bb.y;
            *(__half2*)&g_h[(size_t)r0 * H_ + col]       = __floats2half2_rn(h0, h1);
            *(__half2*)&g_h[(size_t)(r0 + 8) * H_ + col] = __floats2half2_rn(h2, h3);
            sx += mk[2*mi] * h0 + mk[2*mi+1] * h2;
            sy += mk[2*mi] * h1 + mk[2*mi+1] * h3;
            qx += mk[2*mi] * h0 * h0 + mk[2*mi+1] * h2 * h2;
            qy += mk[2*mi] * h1 * h1 + mk[2*mi+1] * h3 * h3;
        }
        #pragma unroll
        for (int o = 4; o < 32; o <<= 1) {
            sx += __shfl_xor_sync(0xffffffffu, sx, o);
            sy += __shfl_xor_sync(0xffffffffu, sy, o);
            qx += __shfl_xor_sync(0xffffffffu, qx, o);
            qy += __shfl_xor_sync(0xffffffffu, qy, o);
        }
        if (lane < 4) {
            atomicAdd(&g_sum[col],       sx);
            atomicAdd(&g_sum[col + 1],   sy);
            atomicAdd(&g_sumsq[col],     qx);
            atomicAdd(&g_sumsq[col + 1], qy);
        }
    }
}

// =====================================================================
// 4) finalize BN affine
// =====================================================================
__global__ void k_finalize(const float* __restrict__ gamma,
                           const float* __restrict__ beta) {
    int tid = threadIdx.x;   // 512 threads
    float nv = 0.f;
    #pragma unroll
    for (int b = 0; b < B_; b++) nv += g_counts[b];
    nv = fmaxf(nv, 1.f);
    float mean = g_sum[tid] / nv;
    float var  = g_sumsq[tid] / nv - mean * mean;
    var = fmaxf(var, 0.f);
    float istd = rsqrtf(var + 1e-5f);
    float sc = istd * gamma[tid];
    g_scale[tid] = sc;
    g_shift[tid] = beta[tid] - mean * sc;
}

// =====================================================================
// 5) masked relu-normalize-pool (fp16 h, branch-free)
// =====================================================================
__global__ __launch_bounds__(128) void k_pool(const int* __restrict__ mask) {
    int tid = threadIdx.x;               // 4-feature group 0..127
    int b = blockIdx.y;
    int base = b * L_ + blockIdx.x * 128;
    float4 sc = ((const float4*)g_scale)[tid];
    float4 sh = ((const float4*)g_shift)[tid];
    float4 acc = make_float4(0.f, 0.f, 0.f, 0.f);
    const uint2* hp = (const uint2*)g_h;     // 4 fp16 per uint2
    for (int r = 0; r < 128; r += 4) {
        int4 m4 = *(const int4*)&mask[base + r];
        float mf[4] = {(float)m4.x, (float)m4.y, (float)m4.z, (float)m4.w};
        uint2 v[4];
        #pragma unroll
        for (int j = 0; j < 4; j++)
            v[j] = hp[(size_t)(base + r + j) * 128 + tid];
        #pragma unroll
        for (int j = 0; j < 4; j++) {
            float2 p0 = __half22float2(*(__half2*)&v[j].x);
            float2 p1 = __half22float2(*(__half2*)&v[j].y);
            acc.x += mf[j] * fmaxf(fmaf(p0.x, sc.x, sh.x), 0.f);
            acc.y += mf[j] * fmaxf(fmaf(p0.y, sc.y, sh.y), 0.f);
            acc.z += mf[j] * fmaxf(fmaf(p1.x, sc.z, sh.z), 0.f);
            acc.w += mf[j] * fmaxf(fmaf(p1.y, sc.w, sh.w), 0.f);
        }
    }
    int f = b * H_ + tid * 4;
    atomicAdd(&g_pooled[f + 0], acc.x);
    atomicAdd(&g_pooled[f + 1], acc.y);
    atomicAdd(&g_pooled[f + 2], acc.z);
    atomicAdd(&g_pooled[f + 3], acc.w);
}

// =====================================================================
// 6) tiny GEMM2
// =====================================================================
__global__ __launch_bounds__(512) void k_gemm2(
    const float* __restrict__ W2,
    const float* __restrict__ b2,
    float* __restrict__ out)
{
    __shared__ float p[H_];
    int b = blockIdx.x;
    int j = threadIdx.x;
    float cnt = fmaxf(g_counts[b], 1.f);
    p[j] = g_pooled[b * H_ + j] / cnt;
    __syncthreads();
    float acc = b2[j];
    #pragma unroll 8
    for (int h = 0; h < H_; h++)
        acc = fmaf(p[h], W2[(size_t)h * H_ + j], acc);
    out[b * H_ + j] = acc;
}

// =====================================================================
extern "C" void kernel_launch(void* const* d_in, const int* in_sizes, int n_in,
                              void* d_out, int out_size) {
    const float* hidden = (const float*)d_in[0];
    const int*   mask   = (const int*)  d_in[1];
    const float* W1     = (const float*)d_in[2];
    const float* b1     = (const float*)d_in[3];
    const float* gamma  = (const float*)d_in[4];
    const float* beta   = (const float*)d_in[5];
    const float* W2     = (const float*)d_in[6];
    const float* b2     = (const float*)d_in[7];
    float* out = (float*)d_out;

    cudaFuncSetAttribute(k_gemm_mma,
                         cudaFuncAttributeMaxDynamicSharedMemorySize, SMEM_GEMM);

    k_zero<<<64, 256>>>();
    k_counts<<<B_, 256>>>(mask);
    k_prepW1<<<(H_ * (D_ / 2) + 255) / 256, 256>>>(W1);
    k_prepA<<<(M_ * D_ / 4 + 255) / 256, 256>>>((const float4*)hidden);
    dim3 g1(H_ / 128, M_ / 128);                 // (4, 512)
    k_gemm_mma<<<g1, 128, SMEM_GEMM>>>(b1, mask);
    k_finalize<<<1, 512>>>(gamma, beta);
    dim3 gp(16, B_);
    k_pool<<<gp, 128>>>(mask);
    k_gemm2<<<B_, 512>>>(W2, b2, out);
}